// round 12
// baseline (speedup 1.0000x reference)
#include <cuda_runtime.h>
#include <math.h>

#define NLOC    2048
#define NTYPE   4
#define RCUT2   36.0f
#define NC1     6               // cells per dim (40/6 = 6.67 > rcut)
#define NCELLS  (NC1*NC1*NC1)   // 216
#define THREADS 1024
#define NWARPS  (THREADS/32)    // 32
#define SLOTCAP 32              // per-neighbor-slot capacity (mean ~9.5)
#define FLATCAP (27*SLOTCAP)    // 864 hard bound after clamping
#define MAXCA   64

__device__ float        g_partials[NCELLS];
__device__ unsigned int g_counter = 0;

// ---------------------------------------------------------------------------
// One block per cell, single-wave. Critical-path-minimized build:
//   ONE scan over atoms -> direct placement into padded per-slot bins
//   warp-shuffle scan of bin counts -> segment offsets
//   27 warps: in-register bitonic sort of their bin + direct compacted
//   build of the image-shifted flat candidate list (no separate passes)
// Pair phase: two warp-tasks per center atom over the flat list (no
// min-image needed — shifts pre-applied; coords used unwrapped, valid to
// ~2 ulp since inputs lie in [0,L) and outputs depend only on min-image
// displacements).
// ---------------------------------------------------------------------------
__global__ __launch_bounds__(THREADS)
void cell_kernel(const float* __restrict__ coord,
                 const int*   __restrict__ atype,
                 const float* __restrict__ box,
                 const float* __restrict__ table,
                 float*       __restrict__ out) {
    __shared__ unsigned char  nmap[NCELLS];        // cell -> neighbor slot
    __shared__ int            cursor[32], segstart[28];
    __shared__ float          sx[27], sy[27], sz[27];
    __shared__ unsigned short padded[27 * SLOTCAP];// raw keys per slot
    __shared__ float4         flat[FLATCAP];       // shifted candidates
    __shared__ float          sh_tab[16];          // pair table
    __shared__ float          sh_sym[16];          // symmetrized table
    __shared__ float4         sh_part[2 * MAXCA];  // per-task partials
    __shared__ float          sh_ae[MAXCA];
    __shared__ float          sh_red[256];
    __shared__ bool           sh_last;

    const int tid  = threadIdx.x;
    const int lane = tid & 31;
    const int wid  = tid >> 5;

    const float Lx = box[0], Ly = box[4], Lz = box[8];
    const float csX = (float)NC1 / Lx, csY = (float)NC1 / Ly, csZ = (float)NC1 / Lz;

    // ---- init ----
    if (tid < NCELLS) nmap[tid] = 0xFF;
    if (tid >= 256 && tid < 272) {
        int t = tid - 256;
        sh_tab[t] = table[t];
        sh_sym[t] = 0.5f * (table[t] + table[(t & 3) * NTYPE + (t >> 2)]);
    }
    __syncthreads();

    const int mycell = blockIdx.x;
    const int cx = mycell % NC1, cy = (mycell / NC1) % NC1, cz = mycell / (NC1 * NC1);
    if (tid < 27) {
        int ox = tid % 3 - 1, oy = (tid / 3) % 3 - 1, oz = tid / 9 - 1;
        int nx = cx + ox, ny = cy + oy, nz = cz + oz;
        float fx = (nx < 0) ? -Lx : (nx >= NC1) ? Lx : 0.0f;
        float fy = (ny < 0) ? -Ly : (ny >= NC1) ? Ly : 0.0f;
        float fz = (nz < 0) ? -Lz : (nz >= NC1) ? Lz : 0.0f;
        nx = (nx + NC1) % NC1; ny = (ny + NC1) % NC1; nz = (nz + NC1) % NC1;
        sx[tid] = fx; sy[tid] = fy; sz[tid] = fz;
        nmap[(nz * NC1 + ny) * NC1 + nx] = (unsigned char)tid;
        cursor[tid] = 0;
    }
    __syncthreads();

    // ---- SINGLE pass over atoms: cell id + direct padded placement ----
    #pragma unroll
    for (int a = tid; a < NLOC; a += THREADS) {
        int ax = min(NC1 - 1, (int)(coord[3 * a + 0] * csX));
        int ay = min(NC1 - 1, (int)(coord[3 * a + 1] * csY));
        int az = min(NC1 - 1, (int)(coord[3 * a + 2] * csZ));
        unsigned char n = nmap[(az * NC1 + ay) * NC1 + ax];
        if (n != 0xFF) {
            int p = atomicAdd(&cursor[n], 1);
            if (p < SLOTCAP)
                padded[(int)n * SLOTCAP + p] = (unsigned short)(((int)n << 11) | a);
        }
    }
    __syncthreads();

    // ---- prefix scan over 27 clamped counts (warp shuffle) ----
    if (tid < 32) {
        int v = (tid < 27) ? min(cursor[tid], SLOTCAP) : 0;
        #pragma unroll
        for (int d = 1; d < 32; d <<= 1) {
            int u = __shfl_up_sync(0xFFFFFFFFu, v, d);
            if (lane >= d) v += u;
        }
        if (tid < 27) segstart[tid + 1] = v;
        if (tid == 0) segstart[0] = 0;
    }
    __syncthreads();

    // ---- 27 warps: bitonic sort bin in registers + build flat directly ----
    if (wid < 27) {
        int seg  = wid;
        int cntc = segstart[seg + 1] - segstart[seg];
        int v = (lane < cntc) ? (int)padded[seg * SLOTCAP + lane] : 0x7FFFFFFF;
        #pragma unroll
        for (int k = 2; k <= 32; k <<= 1) {
            #pragma unroll
            for (int j = k >> 1; j > 0; j >>= 1) {
                int other = __shfl_xor_sync(0xFFFFFFFFu, v, j);
                bool up = ((lane & k) == 0);
                bool hi = ((lane & j) != 0);
                int mn = min(v, other), mx = max(v, other);
                v = (up == hi) ? mx : mn;
            }
        }
        if (lane < cntc) {
            int a = v & 2047;              // sorted ascending by atom index
            flat[segstart[seg] + lane] =
                make_float4(coord[3 * a + 0] + sx[seg],
                            coord[3 * a + 1] + sy[seg],
                            coord[3 * a + 2] + sz[seg],
                            __int_as_float(atype[a] | (a << 2)));
        }
    }
    __syncthreads();

    // ---- pair phase: TWO warp-tasks per center atom ----
    const int total = segstart[27];
    const int cs = segstart[13], ce = segstart[14];   // center cell
    const int m  = ce - cs;
    const float PI_OVER_R = 3.14159265358979323846f / 6.0f;

    for (int task = wid; task < 2 * m; task += NWARPS) {
        int pos  = cs + (task >> 1);
        int half = task & 1;
        float4 pi4 = flat[pos];
        int ti4 = (__float_as_int(pi4.w) & 3) * NTYPE;

        float esum = 0.0f, fxs = 0.0f, fys = 0.0f, fzs = 0.0f;

        for (int j = lane + 32 * half; j < total; j += 64) {
            float4 pj = flat[j];
            float dx = pi4.x - pj.x;           // already minimum-image
            float dy = pi4.y - pj.y;
            float dz = pi4.z - pj.z;
            float r2 = dx * dx + dy * dy + dz * dz;

            if (r2 < RCUT2 && r2 > 0.0f) {     // r2==0 only for self
                float rinv = rsqrtf(r2 + 1e-12f);
                float r    = r2 * rinv;
                int   tj   = __float_as_int(pj.w) & 3;
                float ae   = sh_tab[ti4 + tj];
                float af   = sh_sym[ti4 + tj];

                float t = PI_OVER_R * r;
                float s, c;
                __sincosf(t, &s, &c);
                float sw  = 0.5f * (c + 1.0f);
                float swp = -0.5f * PI_OVER_R * s;

                esum += ae * sw * rinv;
                float fs = af * fmaf(sw, rinv, -swp) * (rinv * rinv);
                fxs += fs * dx;
                fys += fs * dy;
                fzs += fs * dz;
            }
        }

        #pragma unroll
        for (int off = 16; off > 0; off >>= 1) {
            esum += __shfl_xor_sync(0xFFFFFFFFu, esum, off);
            fxs  += __shfl_xor_sync(0xFFFFFFFFu, fxs, off);
            fys  += __shfl_xor_sync(0xFFFFFFFFu, fys, off);
            fzs  += __shfl_xor_sync(0xFFFFFFFFu, fzs, off);
        }
        if (lane == 0 && task < 2 * MAXCA)
            sh_part[task] = make_float4(esum, fxs, fys, fzs);
    }
    __syncthreads();

    // ---- combine halves per atom in fixed order, write outputs ----
    if (tid < m * 4 && tid < MAXCA * 4) {
        int aa = tid >> 2, c = tid & 3;
        const float* p0 = (const float*)&sh_part[2 * aa];
        const float* p1 = (const float*)&sh_part[2 * aa + 1];
        float v = p0[c] + p1[c];
        int orig = (__float_as_int(flat[cs + aa].w)) >> 2;
        if (c == 0) {
            float e = 0.5f * v;
            out[1 + orig] = e;                  // atom_energy
            sh_ae[aa] = e;
        } else {
            float* force = out + 1 + NLOC;
            force[orig * 3 + (c - 1)] = v;
        }
    }
    __syncthreads();

    // ---- total energy: per-block partial + last-block reduce ----
    if (tid == 0) {
        int mm = min(m, MAXCA);
        float p = 0.0f;
        for (int k = 0; k < mm; k++) p += sh_ae[k];
        g_partials[blockIdx.x] = p;
        __threadfence();
        unsigned int old = atomicAdd(&g_counter, 1u);
        sh_last = (old == NCELLS - 1);
    }
    __syncthreads();

    if (sh_last) {
        __threadfence();
        if (tid < 256) {
            volatile float* vp = g_partials;
            sh_red[tid] = (tid < NCELLS) ? vp[tid] : 0.0f;
        }
        __syncthreads();
        #pragma unroll
        for (int s = 128; s > 0; s >>= 1) {
            if (tid < s) sh_red[tid] += sh_red[tid + s];
            __syncthreads();
        }
        if (tid == 0) {
            out[0] = sh_red[0];
            g_counter = 0;                      // reset for next replay
        }
    }
}

// ---------------------------------------------------------------------------
extern "C" void kernel_launch(void* const* d_in, const int* in_sizes, int n_in,
                              void* d_out, int out_size) {
    const float* coord = (const float*)d_in[0];   // (1,2048,3)
    const int*   atype = (const int*)d_in[1];     // (1,2048)
    const float* box   = (const float*)d_in[2];   // (1,3,3)
    const float* table = (const float*)d_in[3];   // (4,4)
    float* out = (float*)d_out;                   // [E(1) | atom_e(2048) | force(2048*3)]

    cell_kernel<<<NCELLS, THREADS>>>(coord, atype, box, table, out);
}

// round 13
// speedup vs baseline: 1.0346x; 1.0346x over previous
#include <cuda_runtime.h>
#include <math.h>

#define NLOC    2048
#define NTYPE   4
#define RCUT2   36.0f
#define NC1     6                // cells per dim (40/6 = 6.67 > rcut)
#define NCELLS  (NC1*NC1*NC1)    // 216
#define NPAIRS  108              // blocks: 2 z-adjacent cells per block
#define NSLOTS  36               // 3x3x4 candidate slab
#define THREADS 1024
#define NWARPS  (THREADS/32)     // 32
#define SLOTCAP 32               // per-slot capacity (mean ~9.5)
#define FLATCAP (NSLOTS*SLOTCAP) // 1152
#define MAXCA   64               // max center atoms per block (mean ~19)

__device__ float        g_partials[NPAIRS];
__device__ unsigned int g_counter = 0;

// ---------------------------------------------------------------------------
// One block per z-adjacent CELL PAIR (108 blocks <= 148 SMs: true single
// wave, one block per SM). Build: single scan over atoms places indices into
// 36 padded slot bins (3x3x4 slab covering both cells' neighborhoods);
// shuffle prefix; 36 warp-bitonic sorts build the compacted image-shifted
// flat list. Pair phase: two warp-tasks per center atom over the shared
// list; extra z-layer candidates are > rcut away and auto-rejected.
// Coords used unwrapped (inputs in [0,L); wrap is a <=2-ulp identity and
// outputs depend only on min-image displacements).
// ---------------------------------------------------------------------------
__global__ __launch_bounds__(THREADS)
void cell_kernel(const float* __restrict__ coord,
                 const int*   __restrict__ atype,
                 const float* __restrict__ box,
                 const float* __restrict__ table,
                 float*       __restrict__ out) {
    __shared__ unsigned char  nmap[NCELLS];         // cell -> slot (0xFF none)
    __shared__ int            cursor[NSLOTS], segstart[NSLOTS + 1];
    __shared__ float          sx[NSLOTS], sy[NSLOTS], sz[NSLOTS];
    __shared__ unsigned short padded[FLATCAP];      // atom index per bin entry
    __shared__ float4         flat[FLATCAP];        // 18KB shifted candidates
    __shared__ float          sh_tab[16];           // pair table
    __shared__ float          sh_sym[16];           // symmetrized table
    __shared__ float4         sh_part[2 * MAXCA];   // per-task partials
    __shared__ float          sh_ae[MAXCA];
    __shared__ float          sh_red[128];
    __shared__ bool           sh_last;

    const int tid  = threadIdx.x;
    const int lane = tid & 31;
    const int wid  = tid >> 5;

    const float Lx = box[0], Ly = box[4], Lz = box[8];
    const float csX = (float)NC1 / Lx, csY = (float)NC1 / Ly, csZ = (float)NC1 / Lz;

    // ---- init ----
    if (tid < NCELLS) nmap[tid] = 0xFF;
    if (tid >= 256 && tid < 272) {
        int t = tid - 256;
        sh_tab[t] = table[t];
        sh_sym[t] = 0.5f * (table[t] + table[(t & 3) * NTYPE + (t >> 2)]);
    }
    __syncthreads();

    const int pid = blockIdx.x;
    const int cx = pid % NC1, cy = (pid / NC1) % NC1, czb = 2 * (pid / 36);
    if (tid < NSLOTS) {
        int ox = tid % 3 - 1, oy = (tid / 3) % 3 - 1, oz = tid / 9 - 1;  // oz in -1..2
        int nx = cx + ox, ny = cy + oy, nz = czb + oz;
        float fx = (nx < 0) ? -Lx : (nx >= NC1) ? Lx : 0.0f;
        float fy = (ny < 0) ? -Ly : (ny >= NC1) ? Ly : 0.0f;
        float fz = (nz < 0) ? -Lz : (nz >= NC1) ? Lz : 0.0f;
        nx = (nx + NC1) % NC1; ny = (ny + NC1) % NC1; nz = (nz + NC1) % NC1;
        sx[tid] = fx; sy[tid] = fy; sz[tid] = fz;
        nmap[(nz * NC1 + ny) * NC1 + nx] = (unsigned char)tid;
        cursor[tid] = 0;
    }
    __syncthreads();

    // ---- SINGLE pass over atoms: cell id + direct padded placement ----
    #pragma unroll
    for (int a = tid; a < NLOC; a += THREADS) {
        int ax = min(NC1 - 1, (int)(coord[3 * a + 0] * csX));
        int ay = min(NC1 - 1, (int)(coord[3 * a + 1] * csY));
        int az = min(NC1 - 1, (int)(coord[3 * a + 2] * csZ));
        unsigned char n = nmap[(az * NC1 + ay) * NC1 + ax];
        if (n != 0xFF) {
            int p = atomicAdd(&cursor[n], 1);
            if (p < SLOTCAP)
                padded[(int)n * SLOTCAP + p] = (unsigned short)a;
        }
    }
    __syncthreads();

    // ---- prefix scan over 36 clamped counts (warp shuffle + fixup) ----
    if (wid == 0) {
        int v = (lane < NSLOTS) ? min(cursor[lane], SLOTCAP) : 0;
        #pragma unroll
        for (int d = 1; d < 32; d <<= 1) {
            int u = __shfl_up_sync(0xFFFFFFFFu, v, d);
            if (lane >= d) v += u;
        }
        segstart[lane + 1] = v;                      // slots 0..31
        int total32 = __shfl_sync(0xFFFFFFFFu, v, 31);
        if (lane == 0) segstart[0] = 0;
        // slots 32..35 (4 values, serial in lane 0 — tiny)
        if (lane == 0) {
            int run = total32;
            #pragma unroll
            for (int s = 32; s < NSLOTS; s++) {
                run += min(cursor[s], SLOTCAP);
                segstart[s + 1] = run;
            }
        }
    }
    __syncthreads();

    // ---- 36 bins: warp-bitonic sort + direct compacted flat build ----
    for (int seg = wid; seg < NSLOTS; seg += NWARPS) {
        int cntc = segstart[seg + 1] - segstart[seg];
        int v = (lane < cntc) ? (int)padded[seg * SLOTCAP + lane] : 0x7FFFFFFF;
        #pragma unroll
        for (int k = 2; k <= 32; k <<= 1) {
            #pragma unroll
            for (int j = k >> 1; j > 0; j >>= 1) {
                int other = __shfl_xor_sync(0xFFFFFFFFu, v, j);
                bool up = ((lane & k) == 0);
                bool hi = ((lane & j) != 0);
                int mn = min(v, other), mx = max(v, other);
                v = (up == hi) ? mx : mn;
            }
        }
        if (lane < cntc) {
            int a = v;                                 // sorted ascending
            flat[segstart[seg] + lane] =
                make_float4(coord[3 * a + 0] + sx[seg],
                            coord[3 * a + 1] + sy[seg],
                            coord[3 * a + 2] + sz[seg],
                            __int_as_float(atype[a] | (a << 2)));
        }
    }
    __syncthreads();

    // ---- pair phase: TWO warp-tasks per center atom (both cells) ----
    const int total = segstart[NSLOTS];
    const int cs13 = segstart[13], m13 = segstart[14] - cs13;  // cell czb
    const int cs22 = segstart[22], m22 = segstart[23] - cs22;  // cell czb+1
    const int m = m13 + m22;
    const float PI_OVER_R = 3.14159265358979323846f / 6.0f;

    for (int task = wid; task < 2 * m; task += NWARPS) {
        int aa   = task >> 1;
        int half = task & 1;
        int pos  = (aa < m13) ? (cs13 + aa) : (cs22 + (aa - m13));
        float4 pi4 = flat[pos];
        int ti4 = (__float_as_int(pi4.w) & 3) * NTYPE;

        float esum = 0.0f, fxs = 0.0f, fys = 0.0f, fzs = 0.0f;

        for (int j = lane + 32 * half; j < total; j += 64) {
            float4 pj = flat[j];
            float dx = pi4.x - pj.x;           // already minimum-image
            float dy = pi4.y - pj.y;
            float dz = pi4.z - pj.z;
            float r2 = dx * dx + dy * dy + dz * dz;

            if (r2 < RCUT2 && r2 > 0.0f) {     // r2==0 only for self
                float rinv = rsqrtf(r2 + 1e-12f);
                float r    = r2 * rinv;
                int   tj   = __float_as_int(pj.w) & 3;
                float ae   = sh_tab[ti4 + tj];
                float af   = sh_sym[ti4 + tj];

                float t = PI_OVER_R * r;
                float s, c;
                __sincosf(t, &s, &c);
                float sw  = 0.5f * (c + 1.0f);
                float swp = -0.5f * PI_OVER_R * s;

                esum += ae * sw * rinv;
                float fs = af * fmaf(sw, rinv, -swp) * (rinv * rinv);
                fxs += fs * dx;
                fys += fs * dy;
                fzs += fs * dz;
            }
        }

        #pragma unroll
        for (int off = 16; off > 0; off >>= 1) {
            esum += __shfl_xor_sync(0xFFFFFFFFu, esum, off);
            fxs  += __shfl_xor_sync(0xFFFFFFFFu, fxs, off);
            fys  += __shfl_xor_sync(0xFFFFFFFFu, fys, off);
            fzs  += __shfl_xor_sync(0xFFFFFFFFu, fzs, off);
        }
        if (lane == 0 && task < 2 * MAXCA)
            sh_part[task] = make_float4(esum, fxs, fys, fzs);
    }
    __syncthreads();

    // ---- combine halves per atom in fixed order, write outputs ----
    if (tid < m * 4 && tid < MAXCA * 4) {
        int aa = tid >> 2, c = tid & 3;
        const float* p0 = (const float*)&sh_part[2 * aa];
        const float* p1 = (const float*)&sh_part[2 * aa + 1];
        float v = p0[c] + p1[c];
        int pos = (aa < m13) ? (cs13 + aa) : (cs22 + (aa - m13));
        int orig = (__float_as_int(flat[pos].w)) >> 2;
        if (c == 0) {
            float e = 0.5f * v;
            out[1 + orig] = e;                  // atom_energy
            sh_ae[aa] = e;
        } else {
            float* force = out + 1 + NLOC;
            force[orig * 3 + (c - 1)] = v;
        }
    }
    __syncthreads();

    // ---- total energy: per-block partial + last-block reduce ----
    if (tid == 0) {
        int mm = min(m, MAXCA);
        float p = 0.0f;
        for (int k = 0; k < mm; k++) p += sh_ae[k];
        g_partials[blockIdx.x] = p;
        __threadfence();
        unsigned int old = atomicAdd(&g_counter, 1u);
        sh_last = (old == NPAIRS - 1);
    }
    __syncthreads();

    if (sh_last) {
        __threadfence();
        if (tid < 128) {
            volatile float* vp = g_partials;
            sh_red[tid] = (tid < NPAIRS) ? vp[tid] : 0.0f;
        }
        __syncthreads();
        #pragma unroll
        for (int s = 64; s > 0; s >>= 1) {
            if (tid < s) sh_red[tid] += sh_red[tid + s];
            __syncthreads();
        }
        if (tid == 0) {
            out[0] = sh_red[0];
            g_counter = 0;                      // reset for next replay
        }
    }
}

// ---------------------------------------------------------------------------
extern "C" void kernel_launch(void* const* d_in, const int* in_sizes, int n_in,
                              void* d_out, int out_size) {
    const float* coord = (const float*)d_in[0];   // (1,2048,3)
    const int*   atype = (const int*)d_in[1];     // (1,2048)
    const float* box   = (const float*)d_in[2];   // (1,3,3)
    const float* table = (const float*)d_in[3];   // (4,4)
    float* out = (float*)d_out;                   // [E(1) | atom_e(2048) | force(2048*3)]

    cell_kernel<<<NPAIRS, THREADS>>>(coord, atype, box, table, out);
}

// round 15
// speedup vs baseline: 1.1662x; 1.1273x over previous
#include <cuda_runtime.h>
#include <math.h>

#define NLOC    2048
#define NTYPE   4
#define RCUT2   36.0f
#define NC1     6                // cells per dim (40/6 = 6.67 > rcut)
#define NPAIRS  108              // blocks: 2 z-adjacent cells per block
#define NSLOTS  36               // 3x3x4 candidate slab
#define THREADS 1024
#define NWARPS  (THREADS/32)     // 32
#define SLOTCAP 32               // per-slot capacity (mean ~9.5)
#define FLATCAP (NSLOTS*SLOTCAP) // 1152
#define MAXCA   64               // center atoms per block (mean ~19)

__device__ float        g_partials[NPAIRS];
__device__ unsigned int g_counter = 0;

// ---------------------------------------------------------------------------
// One block per z-adjacent CELL PAIR (108 blocks, single wave, 1 block/SM).
// Minimal-latency build:
//   SINGLE scan over atoms: slot computed analytically from wrapped cell
//   deltas (no nmap table); shifted float4 stored DIRECTLY into padded bins
//   while coords are in registers (no second gmem pass).
//   Warp-shuffle prefix of 36 bin counts; 36 warp-bitonic sorts on
//   (atom<<5)|binpos keys permute bins into the compacted flat list
//   (deterministic ascending-atom order).
// Pair phase: ONE warp per center atom over the flat list (no min-image —
// shifts pre-applied; coords unwrapped, a <=2-ulp identity for inputs in
// [0,L)). Tail: per-block partial -> last block reduces 108 values in a
// single warp (fixed order).
// ---------------------------------------------------------------------------
__global__ __launch_bounds__(THREADS)
void cell_kernel(const float* __restrict__ coord,
                 const int*   __restrict__ atype,
                 const float* __restrict__ box,
                 const float* __restrict__ table,
                 float*       __restrict__ out) {
    __shared__ int    cursor[NSLOTS], segstart[NSLOTS + 1];
    __shared__ float4 padded[FLATCAP];   // 18KB raw shifted candidates
    __shared__ float4 flat[FLATCAP];     // 18KB compacted candidates
    __shared__ float  sh_tab[16];        // pair table
    __shared__ float  sh_sym[16];        // symmetrized table
    __shared__ float  sh_ae[MAXCA];
    __shared__ bool   sh_last;

    const int tid  = threadIdx.x;
    const int lane = tid & 31;
    const int wid  = tid >> 5;

    const float Lx = box[0], Ly = box[4], Lz = box[8];
    const float csX = (float)NC1 / Lx, csY = (float)NC1 / Ly, csZ = (float)NC1 / Lz;

    const int pid = blockIdx.x;
    const int cx = pid % NC1, cy = (pid / NC1) % NC1, czb = 2 * (pid / 36);

    // ---- init ----
    if (tid < NSLOTS) cursor[tid] = 0;
    if (tid >= 64 && tid < 80) {
        int t = tid - 64;
        sh_tab[t] = table[t];
        sh_sym[t] = 0.5f * (table[t] + table[(t & 3) * NTYPE + (t >> 2)]);
    }
    __syncthreads();

    // ---- SINGLE pass over atoms: analytic slot + direct shifted store ----
    #pragma unroll
    for (int a = tid; a < NLOC; a += THREADS) {
        float x = coord[3 * a + 0];
        float y = coord[3 * a + 1];
        float z = coord[3 * a + 2];
        int ax = min(NC1 - 1, (int)(x * csX));
        int ay = min(NC1 - 1, (int)(y * csY));
        int az = min(NC1 - 1, (int)(z * csZ));
        int vx = ax - cx;  vx += (vx < 0) ? NC1 : 0;   // 0..5
        int vy = ay - cy;  vy += (vy < 0) ? NC1 : 0;
        int vz = az - czb; vz += (vz < 0) ? NC1 : 0;
        bool ok = ((vx <= 1) | (vx == 5)) & ((vy <= 1) | (vy == 5))
                & ((vz <= 2) | (vz == 5));
        if (ok) {
            int ox = (vx == 5) ? -1 : vx;
            int oy = (vy == 5) ? -1 : vy;
            int oz = (vz == 5) ? -1 : vz;
            int slot = (oz + 1) * 9 + (oy + 1) * 3 + (ox + 1);
            int rx = cx + ox, ry = cy + oy, rz = czb + oz;
            float fx = (rx < 0) ? -Lx : (rx >= NC1) ? Lx : 0.0f;
            float fy = (ry < 0) ? -Ly : (ry >= NC1) ? Ly : 0.0f;
            float fz = (rz < 0) ? -Lz : (rz >= NC1) ? Lz : 0.0f;
            int p = atomicAdd(&cursor[slot], 1);
            if (p < SLOTCAP)
                padded[slot * SLOTCAP + p] =
                    make_float4(x + fx, y + fy, z + fz,
                                __int_as_float(atype[a] | (a << 2)));
        }
    }
    __syncthreads();

    // ---- prefix scan over 36 clamped counts (warp 0) ----
    if (wid == 0) {
        int v = (lane < NSLOTS) ? min(cursor[lane], SLOTCAP) : 0;
        #pragma unroll
        for (int d = 1; d < 32; d <<= 1) {
            int u = __shfl_up_sync(0xFFFFFFFFu, v, d);
            if (lane >= d) v += u;
        }
        segstart[lane + 1] = v;
        if (lane == 0) {
            segstart[0] = 0;
            int run = segstart[32];
            #pragma unroll
            for (int s = 32; s < NSLOTS; s++) {
                run += min(cursor[s], SLOTCAP);
                segstart[s + 1] = run;
            }
        }
    }
    __syncthreads();

    // ---- 36 bins: bitonic sort (atom<<5)|pos keys, permute to flat ----
    for (int seg = wid; seg < NSLOTS; seg += NWARPS) {
        int cntc = segstart[seg + 1] - segstart[seg];
        int v;
        if (lane < cntc) {
            int bits = __float_as_int(padded[seg * SLOTCAP + lane].w);
            v = ((bits >> 2) << 5) | lane;       // key: atom index, payload: pos
        } else v = 0x7FFFFFFF;
        #pragma unroll
        for (int k = 2; k <= 32; k <<= 1) {
            #pragma unroll
            for (int j = k >> 1; j > 0; j >>= 1) {
                int other = __shfl_xor_sync(0xFFFFFFFFu, v, j);
                bool up = ((lane & k) == 0);
                bool hi = ((lane & j) != 0);
                int mn = min(v, other), mx = max(v, other);
                v = (up == hi) ? mx : mn;
            }
        }
        if (lane < cntc)
            flat[segstart[seg] + lane] = padded[seg * SLOTCAP + (v & 31)];
    }
    __syncthreads();

    // ---- pair phase: ONE warp per center atom ----
    const int total = segstart[NSLOTS];
    const int cs13 = segstart[13], m13 = segstart[14] - cs13;  // cell czb
    const int cs22 = segstart[22], m22 = segstart[23] - cs22;  // cell czb+1
    const int m = m13 + m22;
    const float PI_OVER_R = 3.14159265358979323846f / 6.0f;

    for (int idx = wid; idx < m; idx += NWARPS) {
        int pos = (idx < m13) ? (cs13 + idx) : (cs22 + (idx - m13));
        float4 pi4 = flat[pos];
        int ti4 = (__float_as_int(pi4.w) & 3) * NTYPE;

        float esum = 0.0f, fxs = 0.0f, fys = 0.0f, fzs = 0.0f;

        for (int j = lane; j < total; j += 32) {
            float4 pj = flat[j];
            float dx = pi4.x - pj.x;           // already minimum-image
            float dy = pi4.y - pj.y;
            float dz = pi4.z - pj.z;
            float r2 = dx * dx + dy * dy + dz * dz;

            if (r2 < RCUT2 && r2 > 0.0f) {     // r2==0 only for self
                float rinv = rsqrtf(r2 + 1e-12f);
                float r    = r2 * rinv;
                int   tj   = __float_as_int(pj.w) & 3;
                float ae   = sh_tab[ti4 + tj];
                float af   = sh_sym[ti4 + tj];

                float t = PI_OVER_R * r;
                float s, c;
                __sincosf(t, &s, &c);
                float sw  = 0.5f * (c + 1.0f);
                float swp = -0.5f * PI_OVER_R * s;

                esum += ae * sw * rinv;
                float fs = af * fmaf(sw, rinv, -swp) * (rinv * rinv);
                fxs += fs * dx;
                fys += fs * dy;
                fzs += fs * dz;
            }
        }

        #pragma unroll
        for (int off = 16; off > 0; off >>= 1) {
            esum += __shfl_xor_sync(0xFFFFFFFFu, esum, off);
            fxs  += __shfl_xor_sync(0xFFFFFFFFu, fxs, off);
            fys  += __shfl_xor_sync(0xFFFFFFFFu, fys, off);
            fzs  += __shfl_xor_sync(0xFFFFFFFFu, fzs, off);
        }

        if (lane == 0) {
            int orig = (__float_as_int(pi4.w)) >> 2;
            float e = 0.5f * esum;
            out[1 + orig] = e;                  // atom_energy
            float* force = out + 1 + NLOC;
            force[orig * 3 + 0] = fxs;
            force[orig * 3 + 1] = fys;
            force[orig * 3 + 2] = fzs;
            if (idx < MAXCA) sh_ae[idx] = e;
        }
    }
    __syncthreads();

    // ---- total energy: per-block partial + last-block single-warp reduce --
    if (tid == 0) {
        int mm = min(m, MAXCA);
        float p = 0.0f;
        for (int k = 0; k < mm; k++) p += sh_ae[k];
        g_partials[blockIdx.x] = p;
        __threadfence();
        unsigned int old = atomicAdd(&g_counter, 1u);
        sh_last = (old == NPAIRS - 1);
    }
    __syncthreads();

    if (sh_last && wid == 0) {
        __threadfence();
        volatile float* vp = g_partials;
        float v = 0.0f;
        #pragma unroll
        for (int k = 0; k < 4; k++) {          // 108 values, fixed order
            int i = lane + 32 * k;
            if (i < NPAIRS) v += vp[i];
        }
        #pragma unroll
        for (int off = 16; off > 0; off >>= 1)
            v += __shfl_xor_sync(0xFFFFFFFFu, v, off);
        if (lane == 0) {
            out[0] = v;
            g_counter = 0;                     // reset for next replay
        }
    }
}

// ---------------------------------------------------------------------------
extern "C" void kernel_launch(void* const* d_in, const int* in_sizes, int n_in,
                              void* d_out, int out_size) {
    const float* coord = (const float*)d_in[0];   // (1,2048,3)
    const int*   atype = (const int*)d_in[1];     // (1,2048)
    const float* box   = (const float*)d_in[2];   // (1,3,3)
    const float* table = (const float*)d_in[3];   // (4,4)
    float* out = (float*)d_out;                   // [E(1) | atom_e(2048) | force(2048*3)]

    cell_kernel<<<NPAIRS, THREADS>>>(coord, atype, box, table, out);
}